// round 5
// baseline (speedup 1.0000x reference)
#include <cuda_runtime.h>
#include <cuda_fp16.h>
#include <cuda_fp8.h>
#include <math.h>

#define BB 8
#define NN 2048
#define DD 128
#define G  16
#define SPLIT 4
#define ROWS_PER_SPLIT (NN / SPLIT)      // 512
#define TWO_PI_F 6.283185307179586f

// Static device scratch (no allocations allowed).
__device__ unsigned char d_C8[(size_t)BB * NN * NN];  // 33.5 MB full coupling, e4m3
__device__ float d_theta_buf[2 * BB * NN];            // ping-pong theta
__device__ float d_trigC[BB * NN];                    // cos(theta)
__device__ float d_trigS[BB * NN];                    // sin(theta)
__device__ float d_partC[BB * G * SPLIT * 128];       // per-(b,g,split) partials
__device__ float d_partS[BB * G * SPLIT * 128];
__device__ int   d_cnt[BB * G];                       // arrival counters (BSS=0)

// ---- packed f32x2 helpers (Blackwell FFMA2) ----
static __device__ __forceinline__ unsigned long long pack2(float lo, float hi) {
    unsigned long long r;
    asm("mov.b64 %0, {%1, %2};" : "=l"(r) : "f"(lo), "f"(hi));
    return r;
}
static __device__ __forceinline__ void unpack2(unsigned long long v, float& lo, float& hi) {
    asm("mov.b64 {%0, %1}, %2;" : "=f"(lo), "=f"(hi) : "l"(v));
}
static __device__ __forceinline__ void fma2(unsigned long long& d,
                                            unsigned long long a,
                                            unsigned long long b) {
    asm("fma.rn.f32x2 %0, %1, %2, %0;" : "+l"(d) : "l"(a), "l"(b));
}

// coupling ≈ x - sqrt(x^2-1), x = max(-lz, 1+1e-7)
__device__ __forceinline__ float coupling_from_lz(float lz) {
    float x = fmaxf(-lz, 1.0f + 1e-7f);
    float t = (x - 1.0f) * (x + 1.0f);
    float xh = 0.5f * t;
    float r = __int_as_float(0x5f375a86 - (__float_as_int(t) >> 1));
    r = r * (1.5f - xh * r * r);
    r = r * (1.5f - xh * r * r);
    r = r * (1.5f - xh * r * r);
    float s = t * r;
    float c = x - s;
    return fminf(fmaxf(c, 0.0f), 1.0f);
}

static __device__ __forceinline__ unsigned fp8x4_from_floats(float c0, float c1,
                                                             float c2, float c3) {
    __nv_fp8x2_storage_t p01 =
        __nv_cvt_float2_to_fp8x2(make_float2(c0, c1), __NV_SATFINITE, __NV_E4M3);
    __nv_fp8x2_storage_t p23 =
        __nv_cvt_float2_to_fp8x2(make_float2(c2, c3), __NV_SATFINITE, __NV_E4M3);
    return (unsigned)p01 | ((unsigned)p23 << 16);
}

#define BM 64
#define BN 64
#define BK 32

// Build C for upper-triangle 128-tiles; strictly-upper blocks also write the
// transposed mirror (step kernels see a FULL symmetric fp8 matrix).
__global__ void build_coupling_kernel(const float* __restrict__ emb) {
    int m128 = blockIdx.x >> 1;
    int n128 = blockIdx.y >> 1;
    if (m128 < n128) return;
    bool twrite = (m128 > n128);

    int b  = blockIdx.z;
    int n0 = blockIdx.y * BM;
    int m0 = blockIdx.x * BN;
    const float* E = emb + (size_t)b * NN * DD;

    __shared__ __align__(16) float As[BK][BM];
    __shared__ __align__(16) float Bs[BK][BN];
    __shared__ unsigned shT[64 * 17];

    int tx = threadIdx.x, ty = threadIdx.y;    // block (16,16)
    int tid = ty * 16 + tx;
    int loadRow = tid >> 3;
    int loadK   = (tid & 7) * 4;

    unsigned long long acc[4][2] = {};

    for (int k0 = 0; k0 < DD; k0 += BK) {
        #pragma unroll
        for (int rr = 0; rr < 2; rr++) {
            int row = loadRow + rr * 32;
            float4 v = *(const float4*)(E + (size_t)(n0 + row) * DD + k0 + loadK);
            if (k0 == 0 && loadK == 0) v.x = -v.x;
            As[loadK + 0][row] = v.x;
            As[loadK + 1][row] = v.y;
            As[loadK + 2][row] = v.z;
            As[loadK + 3][row] = v.w;
            float4 w = *(const float4*)(E + (size_t)(m0 + row) * DD + k0 + loadK);
            Bs[loadK + 0][row] = w.x;
            Bs[loadK + 1][row] = w.y;
            Bs[loadK + 2][row] = w.z;
            Bs[loadK + 3][row] = w.w;
        }
        __syncthreads();

        #pragma unroll
        for (int kk = 0; kk < BK; kk++) {
            float4 a4 = *(const float4*)&As[kk][ty * 4];
            ulonglong2 b2 = *(const ulonglong2*)&Bs[kk][tx * 4];
            unsigned long long a0 = pack2(a4.x, a4.x);
            unsigned long long a1 = pack2(a4.y, a4.y);
            unsigned long long a2 = pack2(a4.z, a4.z);
            unsigned long long a3 = pack2(a4.w, a4.w);
            fma2(acc[0][0], a0, b2.x); fma2(acc[0][1], a0, b2.y);
            fma2(acc[1][0], a1, b2.x); fma2(acc[1][1], a1, b2.y);
            fma2(acc[2][0], a2, b2.x); fma2(acc[2][1], a2, b2.y);
            fma2(acc[3][0], a3, b2.x); fma2(acc[3][1], a3, b2.y);
        }
        __syncthreads();
    }

    #pragma unroll
    for (int i = 0; i < 4; i++) {
        int n = n0 + ty * 4 + i;
        float c0, c1, c2, c3;
        unpack2(acc[i][0], c0, c1);
        unpack2(acc[i][1], c2, c3);
        c0 = coupling_from_lz(c0);
        c1 = coupling_from_lz(c1);
        c2 = coupling_from_lz(c2);
        c3 = coupling_from_lz(c3);
        unsigned o = fp8x4_from_floats(c0, c1, c2, c3);
        *(unsigned*)(d_C8 + ((size_t)b * NN + n) * NN + m0 + tx * 4) = o;
        if (twrite) shT[(ty * 4 + i) * 17 + tx] = o;
    }

    if (twrite) {
        __syncthreads();
        #pragma unroll
        for (int k = 0; k < 4; k++) {
            int idx = k * 256 + tid;
            int mm = idx >> 4;
            int qn = idx & 15;
            int word = mm >> 2, sh = (mm & 3) * 8;
            unsigned u0 = shT[(qn * 4 + 0) * 17 + word];
            unsigned u1 = shT[(qn * 4 + 1) * 17 + word];
            unsigned u2 = shT[(qn * 4 + 2) * 17 + word];
            unsigned u3 = shT[(qn * 4 + 3) * 17 + word];
            unsigned o = ((u0 >> sh) & 0xFFu)
                       | (((u1 >> sh) & 0xFFu) << 8)
                       | (((u2 >> sh) & 0xFFu) << 16)
                       | (((u3 >> sh) & 0xFFu) << 24);
            *(unsigned*)(d_C8 + ((size_t)b * NN + m0 + mm) * NN + n0 + qn * 4) = o;
        }
    }
}

__global__ void init_trig_kernel(const float* __restrict__ th) {
    int i = blockIdx.x * 256 + threadIdx.x;
    float s, c;
    sincosf(th[i], &s, &c);
    d_trigC[i] = c;
    d_trigS[i] = s;
}

// One step, ONE kernel: grid (G, SPLIT, B), 256 threads. Each block streams a
// 512x128 fp8 tile (column-pattern matvec for y_c, y_s), writes its partial to
// a fixed slot; the LAST block per (b,g) sums slots in fixed order (bitwise
// deterministic), does the theta update + next trig, and resets the counter.
__global__ void __launch_bounds__(256, 4)
step_kernel(const float* __restrict__ th_in,
            float* __restrict__ th_out,
            const float* __restrict__ omega) {
    __shared__ __align__(16) float shC[ROWS_PER_SPLIT];
    __shared__ __align__(16) float shS[ROWS_PER_SPLIT];
    __shared__ __align__(16) float shRedC[16 * 132];
    __shared__ __align__(16) float shRedS[16 * 132];
    __shared__ int isLast;

    int g  = blockIdx.x;
    int sp = blockIdx.y;
    int b  = blockIdx.z;
    int tid = threadIdx.x;
    int w = tid >> 5, lane = tid & 31;
    int h = lane >> 4;                 // half-warp row parity
    int co = (lane & 15) * 8;          // this lane's 8 columns

    int r0 = sp * ROWS_PER_SPLIT;
    // stage trig slice for this block's rows
    shC[tid]       = d_trigC[b * NN + r0 + tid];
    shC[tid + 256] = d_trigC[b * NN + r0 + tid + 256];
    shS[tid]       = d_trigS[b * NN + r0 + tid];
    shS[tid + 256] = d_trigS[b * NN + r0 + tid + 256];
    __syncthreads();

    const unsigned char* Cb =
        d_C8 + ((size_t)b * NN + r0 + w * 64) * NN + g * 128 + co;

    unsigned long long accC[4] = {0, 0, 0, 0};
    unsigned long long accS[4] = {0, 0, 0, 0};

    #pragma unroll 8
    for (int p = 0; p < 32; p++) {     // half-warp stream: rows w*64 + 2p + h
        int lr = w * 64 + 2 * p + h;
        uint2 v = *(const uint2*)(Cb + (size_t)(2 * p + h) * NN);

        __half2 h0 = __half2(__nv_cvt_fp8x2_to_halfraw2((__nv_fp8x2_storage_t)(v.x & 0xFFFF), __NV_E4M3));
        __half2 h1 = __half2(__nv_cvt_fp8x2_to_halfraw2((__nv_fp8x2_storage_t)(v.x >> 16),    __NV_E4M3));
        __half2 h2 = __half2(__nv_cvt_fp8x2_to_halfraw2((__nv_fp8x2_storage_t)(v.y & 0xFFFF), __NV_E4M3));
        __half2 h3 = __half2(__nv_cvt_fp8x2_to_halfraw2((__nv_fp8x2_storage_t)(v.y >> 16),    __NV_E4M3));
        float2 f0 = __half22float2(h0);
        float2 f1 = __half22float2(h1);
        float2 f2 = __half22float2(h2);
        float2 f3 = __half22float2(h3);
        unsigned long long C0 = pack2(f0.x, f0.y);
        unsigned long long C1 = pack2(f1.x, f1.y);
        unsigned long long C2 = pack2(f2.x, f2.y);
        unsigned long long C3 = pack2(f3.x, f3.y);

        float cn = shC[lr], sn = shS[lr];
        unsigned long long cnn = pack2(cn, cn);
        unsigned long long snn = pack2(sn, sn);
        fma2(accC[0], C0, cnn); fma2(accC[1], C1, cnn);
        fma2(accC[2], C2, cnn); fma2(accC[3], C3, cnn);
        fma2(accS[0], C0, snn); fma2(accS[1], C1, snn);
        fma2(accS[2], C2, snn); fma2(accS[3], C3, snn);
    }

    // stash per-(warp,half) column partials
    {
        int slot = w * 2 + h;
        float* pc = &shRedC[slot * 132 + co];
        float* ps = &shRedS[slot * 132 + co];
        float x0, x1, x2, x3;
        unpack2(accC[0], x0, x1); unpack2(accC[1], x2, x3);
        *(float4*)pc = make_float4(x0, x1, x2, x3);
        unpack2(accC[2], x0, x1); unpack2(accC[3], x2, x3);
        *(float4*)(pc + 4) = make_float4(x0, x1, x2, x3);
        unpack2(accS[0], x0, x1); unpack2(accS[1], x2, x3);
        *(float4*)ps = make_float4(x0, x1, x2, x3);
        unpack2(accS[2], x0, x1); unpack2(accS[3], x2, x3);
        *(float4*)(ps + 4) = make_float4(x0, x1, x2, x3);
    }
    __syncthreads();

    // reduce 16 slots -> block partial, write to fixed slot
    if (tid < 256) {
        int col = tid & 127;
        const float* base = (tid < 128) ? shRedC : shRedS;
        float acc = 0.0f;
        #pragma unroll
        for (int s = 0; s < 16; s++) acc += base[s * 132 + col];
        size_t idx = (((size_t)(b * G + g)) * SPLIT + sp) * 128 + col;
        if (tid < 128) d_partC[idx] = acc; else d_partS[idx] = acc;
    }
    __syncthreads();

    if (tid == 0) {
        __threadfence();
        int old = atomicAdd(&d_cnt[b * G + g], 1);
        isLast = (old == SPLIT - 1);
    }
    __syncthreads();

    if (isLast) {
        __threadfence();
        if (tid < 128) {
            size_t base = ((size_t)(b * G + g)) * SPLIT * 128 + tid;
            float yc = 0.0f, ys = 0.0f;
            #pragma unroll
            for (int s = 0; s < SPLIT; s++) {     // fixed order -> deterministic
                yc += d_partC[base + (size_t)s * 128];
                ys += d_partS[base + (size_t)s * 128];
            }
            int n  = g * 128 + tid;
            int gi = b * NN + n;
            float sn = d_trigS[gi], cn = d_trigC[gi];
            float csum = sn * yc - cn * ys;
            float dth = omega[n] + (1.0f / NN) * csum;
            float thn = fmodf(th_in[gi] + 0.1f * dth, TWO_PI_F);
            th_out[gi] = thn;
            float s2, c2;
            sincosf(thn, &s2, &c2);
            d_trigC[gi] = c2;
            d_trigS[gi] = s2;
        }
        if (tid == 0) d_cnt[b * G + g] = 0;       // ready for next step/replay
    }
}

extern "C" void kernel_launch(void* const* d_in, const int* in_sizes, int n_in,
                              void* d_out, int out_size) {
    const float* initial = (const float*)d_in[0];   // (B,N)
    const float* emb     = (const float*)d_in[1];   // (B,N,D)
    const float* omega   = (const float*)d_in[2];   // (N,)
    float* out = (float*)d_out;                     // (B,N)

    float* buf = nullptr;
    cudaGetSymbolAddress((void**)&buf, d_theta_buf);

    dim3 bgrid(NN / BN, NN / BM, BB);
    dim3 bblock(16, 16);
    build_coupling_kernel<<<bgrid, bblock>>>(emb);
    init_trig_kernel<<<BB * NN / 256, 256>>>(initial);

    dim3 sgrid(G, SPLIT, BB);
    for (int k = 0; k < 16; k++) {
        const float* src = (k == 0)  ? initial : buf + ((k + 1) & 1) * BB * NN;
        float*       dst = (k == 15) ? out     : buf + (k & 1) * BB * NN;
        step_kernel<<<sgrid, 256>>>(src, dst, omega);
    }
}